// round 1
// baseline (speedup 1.0000x reference)
#include <cuda_runtime.h>
#include <math.h>

// ---------------- problem constants ----------------
#define BATCH 2
#define SEQ   1024
#define DIM   1024
#define HDIM  256
#define MBITS 32
#define NTOK  (BATCH*SEQ)     // 2048
#define PROJ  192             // 6 groups x 32
#define SCALEF 0.17677669529663687f  // 1/sqrt(32)

// ---------------- device scratch (static, no allocs) ----------------
__device__ float    g_Wq[PROJ*DIM];
__device__ float    g_Wk[PROJ*DIM];
__device__ float    g_Bq[PROJ];
__device__ float    g_Bk[PROJ];
__device__ float    g_Wv[4*HDIM*DIM];
__device__ float    g_qproj[NTOK*PROJ];
__device__ float    g_kproj[NTOK*PROJ];
__device__ unsigned g_qbits[NTOK*2];
__device__ unsigned g_kbits[NTOK*2];
__device__ float    g_Vp[NTOK*4*HDIM];
__device__ float    g_cat[NTOK*4*HDIM];

// ---------------- pack weights into fused layouts ----------------
__global__ void pack_weights(
    const float* __restrict__ bq_w, const float* __restrict__ tq_w,
    const float* __restrict__ rq_w, const float* __restrict__ pq_w,
    const float* __restrict__ bq_b, const float* __restrict__ tq_b,
    const float* __restrict__ rq_b, const float* __restrict__ pq_b,
    const float* __restrict__ bk_w, const float* __restrict__ tk_w,
    const float* __restrict__ rk_w, const float* __restrict__ pk_w,
    const float* __restrict__ bk_b, const float* __restrict__ tk_b,
    const float* __restrict__ rk_b, const float* __restrict__ pk_b,
    const float* __restrict__ b_v,  const float* __restrict__ t_v,
    const float* __restrict__ r_v,  const float* __restrict__ p_v)
{
    int i0 = blockIdx.x * blockDim.x + threadIdx.x;
    int stride = gridDim.x * blockDim.x;
    // V weights: rows 0..255 = b_v, 256..511 = t_v, 512..767 = r_v, 768..1023 = p_v
    for (int e = i0; e < 4*HDIM*DIM; e += stride) {
        int h = e >> 10, d = e & 1023;
        float v;
        if (h < 256)      v = b_v[h*DIM + d];
        else if (h < 512) v = t_v[(h-256)*DIM + d];
        else if (h < 768) v = r_v[(h-512)*DIM + d];
        else              v = p_v[(h-768)*DIM + d];
        g_Wv[e] = v;
    }
    // Q/K projection weights: groups [bool, trop, real, p-bool, p-trop, p-real]
    for (int e = i0; e < PROJ*DIM; e += stride) {
        int r = e >> 10, d = e & 1023;
        int g = r >> 5, j = r & 31;
        const float* sq; const float* sk;
        switch (g) {
            case 0: sq = bq_w; sk = bk_w; break;
            case 1: sq = tq_w; sk = tk_w; break;
            case 2: sq = rq_w; sk = rk_w; break;
            default: sq = pq_w + (g-3)*MBITS*DIM; sk = pk_w + (g-3)*MBITS*DIM; break;
        }
        int off = j*DIM + d;
        g_Wq[e] = sq[off];
        g_Wk[e] = sk[off];
    }
    for (int e = i0; e < PROJ; e += stride) {
        int g = e >> 5, j = e & 31;
        float vq, vk;
        switch (g) {
            case 0: vq = bq_b[j]; vk = bk_b[j]; break;
            case 1: vq = tq_b[j]; vk = tk_b[j]; break;
            case 2: vq = rq_b[j]; vk = rk_b[j]; break;
            default: vq = pq_b[(g-3)*MBITS + j]; vk = pk_b[(g-3)*MBITS + j]; break;
        }
        g_Bq[e] = vq;
        g_Bk[e] = vk;
    }
}

// ---------------- generic tiled fp32 GEMM: C[M,N] = A[M,K] * W[N,K]^T + bias ----------------
// 128x128 block tile, BK=16, 256 threads, 8x8 microtile per thread.
__global__ void gemm_kernel(const float* __restrict__ A, const float* __restrict__ W,
                            const float* __restrict__ bias, float* __restrict__ C,
                            int M, int N, int K)
{
    __shared__ __align__(16) float As[16][132];
    __shared__ __align__(16) float Ws[16][132];
    const int bm = blockIdx.y * 128, bn = blockIdx.x * 128;
    const int tid = threadIdx.x;
    const int tx = tid & 15, ty = tid >> 4;
    const int lk = tid & 15, lr = tid >> 4;

    float acc[8][8];
    #pragma unroll
    for (int i = 0; i < 8; ++i)
        #pragma unroll
        for (int j = 0; j < 8; ++j) acc[i][j] = 0.f;

    for (int k0 = 0; k0 < K; k0 += 16) {
        #pragma unroll
        for (int p = 0; p < 8; ++p) {
            int m = lr + p*16;
            As[lk][m] = (bm + m < M) ? A[(size_t)(bm+m)*K + k0 + lk] : 0.f;
            Ws[lk][m] = (bn + m < N) ? W[(size_t)(bn+m)*K + k0 + lk] : 0.f;
        }
        __syncthreads();
        #pragma unroll
        for (int kk = 0; kk < 16; ++kk) {
            float4 a0 = *(const float4*)&As[kk][ty*8];
            float4 a1 = *(const float4*)&As[kk][ty*8+4];
            float4 b0 = *(const float4*)&Ws[kk][tx*8];
            float4 b1 = *(const float4*)&Ws[kk][tx*8+4];
            float a[8] = {a0.x,a0.y,a0.z,a0.w,a1.x,a1.y,a1.z,a1.w};
            float b[8] = {b0.x,b0.y,b0.z,b0.w,b1.x,b1.y,b1.z,b1.w};
            #pragma unroll
            for (int i = 0; i < 8; ++i)
                #pragma unroll
                for (int j = 0; j < 8; ++j)
                    acc[i][j] += a[i]*b[j];
        }
        __syncthreads();
    }
    #pragma unroll
    for (int i = 0; i < 8; ++i) {
        int row = bm + ty*8 + i;
        if (row >= M) continue;
        #pragma unroll
        for (int j = 0; j < 8; ++j) {
            int col = bn + tx*8 + j;
            if (col < N)
                C[(size_t)row*N + col] = acc[i][j] + (bias ? bias[col] : 0.f);
        }
    }
}

// ---------------- bit packing for boolean heads ----------------
__global__ void pack_bits()
{
    int gw = (blockIdx.x * blockDim.x + threadIdx.x) >> 5;
    int lane = threadIdx.x & 31;
    if (gw >= NTOK) return;
    unsigned q0 = __ballot_sync(0xffffffffu, g_qproj[(size_t)gw*PROJ + lane]       > 0.f);
    unsigned q1 = __ballot_sync(0xffffffffu, g_qproj[(size_t)gw*PROJ + 96 + lane]  > 0.f);
    unsigned k0 = __ballot_sync(0xffffffffu, g_kproj[(size_t)gw*PROJ + lane]       > 0.f);
    unsigned k1 = __ballot_sync(0xffffffffu, g_kproj[(size_t)gw*PROJ + 96 + lane]  > 0.f);
    if (lane == 0) {
        g_qbits[gw*2]   = q0; g_qbits[gw*2+1] = q1;
        g_kbits[gw*2]   = k0; g_kbits[gw*2+1] = k1;
    }
}

// ---------------- fused attention (streaming softmax, one head per block) ----------------
__device__ __forceinline__ float wredmax(float v) {
    #pragma unroll
    for (int o = 16; o; o >>= 1) v = fmaxf(v, __shfl_xor_sync(0xffffffffu, v, o));
    return v;
}
__device__ __forceinline__ float wredsum(float v) {
    #pragma unroll
    for (int o = 16; o; o >>= 1) v += __shfl_xor_sync(0xffffffffu, v, o);
    return v;
}

// smem layout (floats): vp[64*256] | sc[16*64] | qe0[16*33] | qe1[16*33] | ke0[64*33] | ke1[64*33] | qb[16] kb[64]
#define ATTN_SMEM_FLOATS (64*256 + 16*64 + 2*16*33 + 2*64*33 + 80)
#define ATTN_SMEM_BYTES  (ATTN_SMEM_FLOATS*4)

__global__ void attn_kernel(const float* __restrict__ t_temp,
                            const float* __restrict__ p_fusion)
{
    extern __shared__ __align__(16) float sm[];
    float* vp  = sm;                 // [64][256]
    float* sc  = vp + 64*256;        // [16][64]
    float* qe0 = sc + 16*64;         // [16][33]
    float* qe1 = qe0 + 16*33;
    float* ke0 = qe1 + 16*33;        // [64][33]
    float* ke1 = ke0 + 64*33;
    unsigned* qb = (unsigned*)(ke1 + 64*33);  // [16]
    unsigned* kb = qb + 16;                    // [64]

    const int n0   = blockIdx.x * 16;
    const int b    = blockIdx.y;
    const int head = blockIdx.z;
    const int tid  = threadIdx.x;
    const int lane = tid & 31;
    const int w    = tid >> 5;       // warp 0..7
    const int q0   = 2*w, q1 = 2*w + 1;

    float inv_sp = 1.f;
    if (head == 1) inv_sp = 1.f / log1pf(expf(t_temp[0]));
    float fw0 = 0.f, fw1 = 0.f, fw2 = 0.f;
    if (head == 3) {
        float p0 = p_fusion[0], p1 = p_fusion[1], p2 = p_fusion[2];
        float mx = fmaxf(p0, fmaxf(p1, p2));
        float e0 = expf(p0-mx), e1 = expf(p1-mx), e2 = expf(p2-mx);
        float inv = 1.f/(e0+e1+e2);
        fw0 = e0*inv; fw1 = e1*inv; fw2 = e2*inv;
    }

    // ---- load query encodings (once) ----
    if (head == 0) {
        if (tid < 16) qb[tid] = g_qbits[(b*SEQ + n0 + tid)*2 + 0];
    } else if (head == 3) {
        if (tid < 16) qb[tid] = g_qbits[(b*SEQ + n0 + tid)*2 + 1];
        for (int j = tid; j < 512; j += 256) {
            int t = j >> 5, m = j & 31;
            const float* base = &g_qproj[(size_t)(b*SEQ + n0 + t)*PROJ];
            qe0[t*33+m] = base[128+m];
            qe1[t*33+m] = base[160+m];
        }
    } else {
        int off = (head == 1) ? 32 : 64;
        for (int j = tid; j < 512; j += 256) {
            int t = j >> 5, m = j & 31;
            qe0[t*33+m] = g_qproj[(size_t)(b*SEQ + n0 + t)*PROJ + off + m];
        }
    }

    float m0r = -INFINITY, m1r = -INFINITY;
    float l0r = 0.f, l1r = 0.f;
    float acc0[8], acc1[8];
    #pragma unroll
    for (int j = 0; j < 8; ++j) { acc0[j] = 0.f; acc1[j] = 0.f; }

    const float* vp_g = &g_Vp[(size_t)(b*SEQ)*1024 + head*HDIM];

    for (int k0i = 0; k0i < SEQ; k0i += 64) {
        __syncthreads();  // prev-tile consumers done before overwriting smem

        // ---- load Vp tile [64 keys][256 cols] ----
        #pragma unroll
        for (int i = 0; i < 16; ++i) {
            int idx = tid + 256*i;           // float4 index == row*64 + c4
            int row = idx >> 6, c4 = idx & 63;
            ((float4*)vp)[idx] = *(const float4*)&vp_g[(size_t)(k0i+row)*1024 + c4*4];
        }
        // ---- load key encodings ----
        if (head == 0) {
            if (tid < 64) kb[tid] = g_kbits[(b*SEQ + k0i + tid)*2 + 0];
        } else if (head == 3) {
            if (tid < 64) kb[tid] = g_kbits[(b*SEQ + k0i + tid)*2 + 1];
            for (int j = tid; j < 2048; j += 256) {
                int t = j >> 5, m = j & 31;
                const float* base = &g_kproj[(size_t)(b*SEQ + k0i + t)*PROJ];
                ke0[t*33+m] = base[128+m];
                ke1[t*33+m] = base[160+m];
            }
        } else {
            int off = (head == 1) ? 32 : 64;
            for (int j = tid; j < 2048; j += 256) {
                int t = j >> 5, m = j & 31;
                ke0[t*33+m] = g_kproj[(size_t)(b*SEQ + k0i + t)*PROJ + off + m];
            }
        }
        __syncthreads();

        // ---- scores: 4 per thread into sc[16][64] ----
        #pragma unroll
        for (int i = 0; i < 4; ++i) {
            int idx = tid + 256*i;
            int q = idx >> 6, k = idx & 63;
            float s;
            if (head == 0) {
                int p = __popc(qb[q] ^ kb[k]);
                s = (1.f - p*(1.f/32.f)) * SCALEF;
            } else if (head == 1) {
                float mn = INFINITY;
                #pragma unroll
                for (int m = 0; m < 32; ++m)
                    mn = fminf(mn, qe0[q*33+m] + ke0[k*33+m]);
                s = -mn * inv_sp;
            } else if (head == 2) {
                float d = 0.f;
                #pragma unroll
                for (int m = 0; m < 32; ++m)
                    d += qe0[q*33+m] * ke0[k*33+m];
                s = d * SCALEF;
            } else {
                int p = __popc(qb[q] ^ kb[k]);
                float simb = 1.f - p*(1.f/32.f);
                float mn = INFINITY; float d = 0.f;
                #pragma unroll
                for (int m = 0; m < 32; ++m) {
                    mn = fminf(mn, qe0[q*33+m] + ke0[k*33+m]);
                    d += qe1[q*33+m] * ke1[k*33+m];
                }
                s = (fw0*simb + fw1*(-mn) + fw2*d) * SCALEF;
            }
            sc[idx] = s;
        }
        __syncthreads();

        // ---- per-warp online softmax for queries q0,q1 ----
        float s0a = sc[q0*64 + lane], s0b = sc[q0*64 + lane + 32];
        float s1a = sc[q1*64 + lane], s1b = sc[q1*64 + lane + 32];
        float tm0 = wredmax(fmaxf(s0a, s0b));
        float tm1 = wredmax(fmaxf(s1a, s1b));
        float mn0 = fmaxf(m0r, tm0), mn1 = fmaxf(m1r, tm1);
        float c0 = expf(m0r - mn0), c1 = expf(m1r - mn1);
        float p0a = expf(s0a - mn0), p0b = expf(s0b - mn0);
        float p1a = expf(s1a - mn1), p1b = expf(s1b - mn1);
        sc[q0*64 + lane] = p0a; sc[q0*64 + lane + 32] = p0b;
        sc[q1*64 + lane] = p1a; sc[q1*64 + lane + 32] = p1b;
        l0r = l0r*c0 + wredsum(p0a + p0b);
        l1r = l1r*c1 + wredsum(p1a + p1b);
        m0r = mn0; m1r = mn1;
        #pragma unroll
        for (int j = 0; j < 8; ++j) { acc0[j] *= c0; acc1[j] *= c1; }
        __syncwarp();

        // ---- P*V rank updates ----
        #pragma unroll 4
        for (int k = 0; k < 64; ++k) {
            float pw0 = sc[q0*64 + k];
            float pw1 = sc[q1*64 + k];
            float4 v0 = *(const float4*)&vp[k*256 + lane*8];
            float4 v1 = *(const float4*)&vp[k*256 + lane*8 + 4];
            acc0[0] += pw0*v0.x; acc0[1] += pw0*v0.y; acc0[2] += pw0*v0.z; acc0[3] += pw0*v0.w;
            acc0[4] += pw0*v1.x; acc0[5] += pw0*v1.y; acc0[6] += pw0*v1.z; acc0[7] += pw0*v1.w;
            acc1[0] += pw1*v0.x; acc1[1] += pw1*v0.y; acc1[2] += pw1*v0.z; acc1[3] += pw1*v0.w;
            acc1[4] += pw1*v1.x; acc1[5] += pw1*v1.y; acc1[6] += pw1*v1.z; acc1[7] += pw1*v1.w;
        }
    }

    // ---- epilogue: normalize + write to cat buffer ----
    float il0 = 1.f/l0r, il1 = 1.f/l1r;
    float* o0 = &g_cat[(size_t)(b*SEQ + n0 + q0)*1024 + head*HDIM + lane*8];
    float* o1 = &g_cat[(size_t)(b*SEQ + n0 + q1)*1024 + head*HDIM + lane*8];
    #pragma unroll
    for (int j = 0; j < 8; ++j) { o0[j] = acc0[j]*il0; o1[j] = acc1[j]*il1; }
}

// ---------------- host launch ----------------
extern "C" void kernel_launch(void* const* d_in, const int* in_sizes, int n_in,
                              void* d_out, int out_size)
{
    const float* Q        = (const float*)d_in[0];
    const float* K        = (const float*)d_in[1];
    const float* V        = (const float*)d_in[2];
    const float* bq_w     = (const float*)d_in[3];
    const float* bq_b     = (const float*)d_in[4];
    const float* bk_w     = (const float*)d_in[5];
    const float* bk_b     = (const float*)d_in[6];
    const float* b_v      = (const float*)d_in[7];
    const float* tq_w     = (const float*)d_in[8];
    const float* tq_b     = (const float*)d_in[9];
    const float* tk_w     = (const float*)d_in[10];
    const float* tk_b     = (const float*)d_in[11];
    const float* t_v      = (const float*)d_in[12];
    const float* t_temp   = (const float*)d_in[13];
    const float* rq_w     = (const float*)d_in[14];
    const float* rq_b     = (const float*)d_in[15];
    const float* rk_w     = (const float*)d_in[16];
    const float* rk_b     = (const float*)d_in[17];
    const float* r_v      = (const float*)d_in[18];
    const float* pq_w     = (const float*)d_in[19];
    const float* pq_b     = (const float*)d_in[20];
    const float* pk_w     = (const float*)d_in[21];
    const float* pk_b     = (const float*)d_in[22];
    const float* p_v      = (const float*)d_in[23];
    const float* p_fusion = (const float*)d_in[24];
    const float* out_w    = (const float*)d_in[25];
    const float* out_b    = (const float*)d_in[26];
    float* out = (float*)d_out;

    void *pWq, *pWk, *pBq, *pBk, *pWv, *pqp, *pkp, *pVp, *pcat;
    cudaGetSymbolAddress(&pWq,  g_Wq);
    cudaGetSymbolAddress(&pWk,  g_Wk);
    cudaGetSymbolAddress(&pBq,  g_Bq);
    cudaGetSymbolAddress(&pBk,  g_Bk);
    cudaGetSymbolAddress(&pWv,  g_Wv);
    cudaGetSymbolAddress(&pqp,  g_qproj);
    cudaGetSymbolAddress(&pkp,  g_kproj);
    cudaGetSymbolAddress(&pVp,  g_Vp);
    cudaGetSymbolAddress(&pcat, g_cat);

    pack_weights<<<256, 256>>>(bq_w, tq_w, rq_w, pq_w, bq_b, tq_b, rq_b, pq_b,
                               bk_w, tk_w, rk_w, pk_w, bk_b, tk_b, rk_b, pk_b,
                               b_v, t_v, r_v, p_v);

    // Q/K projections: [2048 x 192 x 1024]
    gemm_kernel<<<dim3(2, 16), 256>>>(Q, (const float*)pWq, (const float*)pBq,
                                      (float*)pqp, NTOK, PROJ, DIM);
    gemm_kernel<<<dim3(2, 16), 256>>>(K, (const float*)pWk, (const float*)pBk,
                                      (float*)pkp, NTOK, PROJ, DIM);
    // V projection: [2048 x 1024 x 1024]
    gemm_kernel<<<dim3(8, 16), 256>>>(V, (const float*)pWv, nullptr,
                                      (float*)pVp, NTOK, 4*HDIM, DIM);
    pack_bits<<<NTOK*32/256, 256>>>();

    cudaFuncSetAttribute(attn_kernel, cudaFuncAttributeMaxDynamicSharedMemorySize,
                         ATTN_SMEM_BYTES);
    attn_kernel<<<dim3(SEQ/16, BATCH, 4), 256, ATTN_SMEM_BYTES>>>(t_temp, p_fusion);

    // output projection: [2048 x 1024 x 1024]
    gemm_kernel<<<dim3(8, 16), 256>>>((const float*)pcat, out_w, out_b,
                                      out, NTOK, DIM, DIM);
}

// round 2
// speedup vs baseline: 1.6795x; 1.6795x over previous
#include <cuda_runtime.h>
#include <math.h>

// ---------------- problem constants ----------------
#define BATCH 2
#define SEQ   1024
#define DIM   1024
#define HDIM  256
#define MBITS 32
#define NTOK  (BATCH*SEQ)     // 2048
#define PROJ  192             // 6 groups x 32
#define SCALEF 0.17677669529663687f  // 1/sqrt(32)

// ---------------- device scratch (static, no allocs) ----------------
__device__ float    g_Wq[PROJ*DIM];
__device__ float    g_Wk[PROJ*DIM];
__device__ float    g_Bq[PROJ];
__device__ float    g_Bk[PROJ];
__device__ float    g_Wv[4*HDIM*DIM];
__device__ float    g_qproj[NTOK*PROJ];
__device__ float    g_kproj[NTOK*PROJ];
__device__ unsigned g_qbits[NTOK*2];
__device__ unsigned g_kbits[NTOK*2];
__device__ float    g_Vp[NTOK*4*HDIM];
__device__ float    g_cat[NTOK*4*HDIM];

// ---------------- pack weights into fused layouts ----------------
__global__ void pack_weights(
    const float* __restrict__ bq_w, const float* __restrict__ tq_w,
    const float* __restrict__ rq_w, const float* __restrict__ pq_w,
    const float* __restrict__ bq_b, const float* __restrict__ tq_b,
    const float* __restrict__ rq_b, const float* __restrict__ pq_b,
    const float* __restrict__ bk_w, const float* __restrict__ tk_w,
    const float* __restrict__ rk_w, const float* __restrict__ pk_w,
    const float* __restrict__ bk_b, const float* __restrict__ tk_b,
    const float* __restrict__ rk_b, const float* __restrict__ pk_b,
    const float* __restrict__ b_v,  const float* __restrict__ t_v,
    const float* __restrict__ r_v,  const float* __restrict__ p_v)
{
    int i0 = blockIdx.x * blockDim.x + threadIdx.x;
    int stride = gridDim.x * blockDim.x;
    for (int e = i0; e < 4*HDIM*DIM; e += stride) {
        int h = e >> 10, d = e & 1023;
        float v;
        if (h < 256)      v = b_v[h*DIM + d];
        else if (h < 512) v = t_v[(h-256)*DIM + d];
        else if (h < 768) v = r_v[(h-512)*DIM + d];
        else              v = p_v[(h-768)*DIM + d];
        g_Wv[e] = v;
    }
    for (int e = i0; e < PROJ*DIM; e += stride) {
        int r = e >> 10, d = e & 1023;
        int g = r >> 5, j = r & 31;
        const float* sq; const float* sk;
        switch (g) {
            case 0: sq = bq_w; sk = bk_w; break;
            case 1: sq = tq_w; sk = tk_w; break;
            case 2: sq = rq_w; sk = rk_w; break;
            default: sq = pq_w + (g-3)*MBITS*DIM; sk = pk_w + (g-3)*MBITS*DIM; break;
        }
        int off = j*DIM + d;
        g_Wq[e] = sq[off];
        g_Wk[e] = sk[off];
    }
    for (int e = i0; e < PROJ; e += stride) {
        int g = e >> 5, j = e & 31;
        float vq, vk;
        switch (g) {
            case 0: vq = bq_b[j]; vk = bk_b[j]; break;
            case 1: vq = tq_b[j]; vk = tk_b[j]; break;
            case 2: vq = rq_b[j]; vk = rk_b[j]; break;
            default: vq = pq_b[(g-3)*MBITS + j]; vk = pk_b[(g-3)*MBITS + j]; break;
        }
        g_Bq[e] = vq;
        g_Bk[e] = vk;
    }
}

// ---------------- double-buffered tiled fp32 GEMM ----------------
// C[M,N] = A[M,K] * W[N,K]^T + bias.  BN=128 fixed, BK=8, 256 threads.
// BM in {128 (TM=8), 64 (TM=4)}. blockIdx.z selects (A0,W0,b0,C0) vs (A1,...).
template<int BM, int TM>
__global__ __launch_bounds__(256) void gemm_db(
    const float* __restrict__ A0, const float* __restrict__ A1,
    const float* __restrict__ W0, const float* __restrict__ W1,
    const float* __restrict__ b0, const float* __restrict__ b1,
    float* __restrict__ C0, float* __restrict__ C1,
    int M, int N, int K)
{
    __shared__ __align__(16) float As[2][8][BM+4];
    __shared__ __align__(16) float Ws[2][8][132];

    const float* A    = blockIdx.z ? A1 : A0;
    const float* W    = blockIdx.z ? W1 : W0;
    const float* bias = blockIdx.z ? b1 : b0;
    float*       C    = blockIdx.z ? C1 : C0;

    const int bm = blockIdx.y * BM, bn = blockIdx.x * 128;
    const int tid = threadIdx.x;
    const int tx = tid & 15, ty = tid >> 4;
    const int lrow = tid >> 1, lc4 = (tid & 1) * 4;

    const bool aact = (tid < BM*2);
    const bool wact = (bn + lrow) < N;
    const float* Aptr = A + (size_t)(bm + lrow)*K + lc4;
    const float* Wptr = W + (size_t)(bn + lrow)*K + lc4;

    float acc[TM][8];
    #pragma unroll
    for (int i = 0; i < TM; ++i)
        #pragma unroll
        for (int j = 0; j < 8; ++j) acc[i][j] = 0.f;

    const int nt = K >> 3;
    float4 areg = make_float4(0,0,0,0), wreg = make_float4(0,0,0,0);
    if (aact) areg = *(const float4*)Aptr;
    if (wact) wreg = *(const float4*)Wptr;
    #pragma unroll
    for (int j = 0; j < 4; ++j) {
        if (aact) As[0][lc4+j][lrow] = (&areg.x)[j];
        Ws[0][lc4+j][lrow] = (&wreg.x)[j];
    }
    __syncthreads();

    for (int t = 0; t < nt; ++t) {
        const int cur = t & 1;
        if (t + 1 < nt) {
            if (aact) areg = *(const float4*)(Aptr + (t+1)*8);
            if (wact) wreg = *(const float4*)(Wptr + (t+1)*8);
        }
        #pragma unroll
        for (int kk = 0; kk < 8; ++kk) {
            float a[TM], b[8];
            *(float4*)&b[0] = *(const float4*)&Ws[cur][kk][tx*8];
            *(float4*)&b[4] = *(const float4*)&Ws[cur][kk][tx*8+4];
            *(float4*)&a[0] = *(const float4*)&As[cur][kk][ty*TM];
            if (TM == 8) *(float4*)&a[4] = *(const float4*)&As[cur][kk][ty*TM+4];
            #pragma unroll
            for (int i = 0; i < TM; ++i)
                #pragma unroll
                for (int j = 0; j < 8; ++j)
                    acc[i][j] += a[i]*b[j];
        }
        if (t + 1 < nt) {
            const int nxt = cur ^ 1;
            #pragma unroll
            for (int j = 0; j < 4; ++j) {
                if (aact) As[nxt][lc4+j][lrow] = (&areg.x)[j];
                Ws[nxt][lc4+j][lrow] = (&wreg.x)[j];
            }
        }
        __syncthreads();
    }

    #pragma unroll
    for (int i = 0; i < TM; ++i) {
        int row = bm + ty*TM + i;
        #pragma unroll
        for (int j4 = 0; j4 < 2; ++j4) {
            int col = bn + tx*8 + j4*4;
            if (col < N) {
                float4 o;
                o.x = acc[i][j4*4+0]; o.y = acc[i][j4*4+1];
                o.z = acc[i][j4*4+2]; o.w = acc[i][j4*4+3];
                if (bias) { o.x += bias[col]; o.y += bias[col+1]; o.z += bias[col+2]; o.w += bias[col+3]; }
                *(float4*)&C[(size_t)row*N + col] = o;
            }
        }
    }
}

// ---------------- bit packing for boolean heads ----------------
__global__ void pack_bits()
{
    int gw = (blockIdx.x * blockDim.x + threadIdx.x) >> 5;
    int lane = threadIdx.x & 31;
    if (gw >= NTOK) return;
    unsigned q0 = __ballot_sync(0xffffffffu, g_qproj[(size_t)gw*PROJ + lane]       > 0.f);
    unsigned q1 = __ballot_sync(0xffffffffu, g_qproj[(size_t)gw*PROJ + 96 + lane]  > 0.f);
    unsigned k0 = __ballot_sync(0xffffffffu, g_kproj[(size_t)gw*PROJ + lane]       > 0.f);
    unsigned k1 = __ballot_sync(0xffffffffu, g_kproj[(size_t)gw*PROJ + 96 + lane]  > 0.f);
    if (lane == 0) {
        g_qbits[gw*2]   = q0; g_qbits[gw*2+1] = q1;
        g_kbits[gw*2]   = k0; g_kbits[gw*2+1] = k1;
    }
}

// ---------------- fused attention: 64 queries x 1 head per block ----------------
__device__ __forceinline__ float wredmax(float v) {
    #pragma unroll
    for (int o = 16; o; o >>= 1) v = fmaxf(v, __shfl_xor_sync(0xffffffffu, v, o));
    return v;
}
__device__ __forceinline__ float wredsum(float v) {
    #pragma unroll
    for (int o = 16; o; o >>= 1) v += __shfl_xor_sync(0xffffffffu, v, o);
    return v;
}

// smem floats: vp 16384 | sc 4096 | qe0 2112 | qe1 2112 | ke0 2112 | ke1 2112 | msm 64 | lsm 64 | cf 64 | qb 64 | kb 64
#define ATTN_SMEM_FLOATS (16384 + 4096 + 4*2112 + 3*64 + 128)
#define ATTN_SMEM_BYTES  (ATTN_SMEM_FLOATS*4)

__global__ __launch_bounds__(256) void attn_kernel(const float* __restrict__ t_temp,
                                                   const float* __restrict__ p_fusion)
{
    extern __shared__ __align__(16) float sm[];
    float* vp  = sm;                  // [64][256]
    float* sc  = vp + 16384;          // [64][64]
    float* qe0 = sc + 4096;           // [64][33]
    float* qe1 = qe0 + 2112;
    float* ke0 = qe1 + 2112;          // [64][33]
    float* ke1 = ke0 + 2112;
    float* msm = ke1 + 2112;          // [64]
    float* lsm = msm + 64;
    float* cf  = lsm + 64;
    unsigned* qb = (unsigned*)(cf + 64);   // [64]
    unsigned* kb = qb + 64;                // [64]

    const int n0   = blockIdx.x * 64;
    const int b    = blockIdx.y;
    const int head = blockIdx.z;
    const int tid  = threadIdx.x;
    const int lane = tid & 31;
    const int w    = tid >> 5;

    float inv_sp = 1.f;
    if (head == 1) inv_sp = 1.f / log1pf(expf(t_temp[0]));
    float fw0 = 0.f, fw1 = 0.f, fw2 = 0.f;
    if (head == 3) {
        float p0 = p_fusion[0], p1 = p_fusion[1], p2 = p_fusion[2];
        float mx = fmaxf(p0, fmaxf(p1, p2));
        float e0 = expf(p0-mx), e1 = expf(p1-mx), e2 = expf(p2-mx);
        float inv = 1.f/(e0+e1+e2);
        fw0 = e0*inv; fw1 = e1*inv; fw2 = e2*inv;
    }

    // init softmax state
    if (tid < 64) { msm[tid] = -INFINITY; lsm[tid] = 0.f; }

    // ---- load query encodings once ----
    if (head == 0) {
        if (tid < 64) qb[tid] = g_qbits[(b*SEQ + n0 + tid)*2 + 0];
    } else if (head == 3) {
        if (tid < 64) qb[tid] = g_qbits[(b*SEQ + n0 + tid)*2 + 1];
        for (int j = tid; j < 2048; j += 256) {
            int t = j >> 5, m = j & 31;
            const float* base = &g_qproj[(size_t)(b*SEQ + n0 + t)*PROJ];
            qe0[t*33+m] = base[128+m];
            qe1[t*33+m] = base[160+m];
        }
    } else {
        int off = (head == 1) ? 32 : 64;
        for (int j = tid; j < 2048; j += 256) {
            int t = j >> 5, m = j & 31;
            qe0[t*33+m] = g_qproj[(size_t)(b*SEQ + n0 + t)*PROJ + off + m];
        }
    }

    // PV accumulators: warp handles 16 queries x 4 columns
    const int qg = w >> 1;            // 0..3 query group (16 q each)
    const int hh = w & 1;             // 0/1 column half (128 cols each)
    float acc[16][4];
    #pragma unroll
    for (int i = 0; i < 16; ++i)
        #pragma unroll
        for (int j = 0; j < 4; ++j) acc[i][j] = 0.f;

    const float* vp_g = &g_Vp[(size_t)(b*SEQ)*1024 + head*HDIM];
    const int kk  = tid & 63;         // score-phase key index (fixed per thread)
    const int qb4 = tid >> 6;         // score-phase query sub-block

    for (int k0i = 0; k0i < SEQ; k0i += 64) {
        __syncthreads();  // prior-tile PV done before overwriting smem

        // ---- load Vp tile [64][256] ----
        #pragma unroll
        for (int i = 0; i < 16; ++i) {
            int idx = tid + 256*i;
            int row = idx >> 6, c4 = idx & 63;
            ((float4*)vp)[idx] = *(const float4*)&vp_g[(size_t)(k0i+row)*1024 + c4*4];
        }
        // ---- load key encodings ----
        if (head == 0) {
            if (tid < 64) kb[tid] = g_kbits[(b*SEQ + k0i + tid)*2 + 0];
        } else if (head == 3) {
            if (tid < 64) kb[tid] = g_kbits[(b*SEQ + k0i + tid)*2 + 1];
            for (int j = tid; j < 2048; j += 256) {
                int t = j >> 5, m = j & 31;
                const float* base = &g_kproj[(size_t)(b*SEQ + k0i + t)*PROJ];
                ke0[t*33+m] = base[128+m];
                ke1[t*33+m] = base[160+m];
            }
        } else {
            int off = (head == 1) ? 32 : 64;
            for (int j = tid; j < 2048; j += 256) {
                int t = j >> 5, m = j & 31;
                ke0[t*33+m] = g_kproj[(size_t)(b*SEQ + k0i + t)*PROJ + off + m];
            }
        }
        __syncthreads();

        // ---- scores: thread = fixed key kk, 16 queries ----
        if (head == 0) {
            unsigned kr = kb[kk];
            #pragma unroll
            for (int i = 0; i < 16; ++i) {
                int q = qb4*16 + i;
                int p = __popc(qb[q] ^ kr);
                sc[q*64 + kk] = (1.f - p*(1.f/32.f)) * SCALEF;
            }
        } else if (head == 1) {
            float kr[32];
            #pragma unroll
            for (int m = 0; m < 32; ++m) kr[m] = ke0[kk*33+m];
            #pragma unroll 4
            for (int i = 0; i < 16; ++i) {
                int q = qb4*16 + i;
                const float* qe = &qe0[q*33];
                float mna = INFINITY, mnb = INFINITY;
                #pragma unroll
                for (int m = 0; m < 32; m += 2) {
                    mna = fminf(mna, qe[m]   + kr[m]);
                    mnb = fminf(mnb, qe[m+1] + kr[m+1]);
                }
                sc[q*64 + kk] = -fminf(mna, mnb) * inv_sp;
            }
        } else if (head == 2) {
            float kr[32];
            #pragma unroll
            for (int m = 0; m < 32; ++m) kr[m] = ke0[kk*33+m];
            #pragma unroll 4
            for (int i = 0; i < 16; ++i) {
                int q = qb4*16 + i;
                const float* qe = &qe0[q*33];
                float da = 0.f, db = 0.f;
                #pragma unroll
                for (int m = 0; m < 32; m += 2) {
                    da = fmaf(qe[m],   kr[m],   da);
                    db = fmaf(qe[m+1], kr[m+1], db);
                }
                sc[q*64 + kk] = (da + db) * SCALEF;
            }
        } else {
            float kr0[32], kr1[32];
            #pragma unroll
            for (int m = 0; m < 32; ++m) { kr0[m] = ke0[kk*33+m]; kr1[m] = ke1[kk*33+m]; }
            unsigned kr = kb[kk];
            #pragma unroll 2
            for (int i = 0; i < 16; ++i) {
                int q = qb4*16 + i;
                const float* qe_t = &qe0[q*33];
                const float* qe_r = &qe1[q*33];
                float simb = 1.f - __popc(qb[q] ^ kr)*(1.f/32.f);
                float mna = INFINITY, mnb = INFINITY;
                float da = 0.f, db = 0.f;
                #pragma unroll
                for (int m = 0; m < 32; m += 2) {
                    mna = fminf(mna, qe_t[m]   + kr0[m]);
                    mnb = fminf(mnb, qe_t[m+1] + kr0[m+1]);
                    da = fmaf(qe_r[m],   kr1[m],   da);
                    db = fmaf(qe_r[m+1], kr1[m+1], db);
                }
                sc[q*64 + kk] = (fw0*simb - fw1*fminf(mna,mnb) + fw2*(da+db)) * SCALEF;
            }
        }
        __syncthreads();

        // ---- online softmax: warp w handles rows w*8 .. w*8+7 ----
        #pragma unroll
        for (int j = 0; j < 8; ++j) {
            int q = w*8 + j;
            float s0 = sc[q*64 + lane], s1 = sc[q*64 + lane + 32];
            float tm = wredmax(fmaxf(s0, s1));
            float mold = msm[q];
            float mnew = fmaxf(mold, tm);
            float c  = __expf(mold - mnew);
            float p0 = __expf(s0 - mnew), p1 = __expf(s1 - mnew);
            sc[q*64 + lane] = p0; sc[q*64 + lane + 32] = p1;
            float ls = wredsum(p0 + p1);
            if (lane == 0) { msm[q] = mnew; lsm[q] = lsm[q]*c + ls; cf[q] = c; }
        }
        __syncthreads();

        // ---- P*V: warp = 16 queries (qg) x 4 cols/lane (hh half) ----
        #pragma unroll
        for (int i = 0; i < 16; ++i) {
            float c = cf[qg*16 + i];
            #pragma unroll
            for (int j = 0; j < 4; ++j) acc[i][j] *= c;
        }
        const float* vbase = vp + hh*128 + lane*4;
        #pragma unroll 4
        for (int k4 = 0; k4 < 16; ++k4) {
            float4 v0 = *(const float4*)(vbase + (k4*4+0)*256);
            float4 v1 = *(const float4*)(vbase + (k4*4+1)*256);
            float4 v2 = *(const float4*)(vbase + (k4*4+2)*256);
            float4 v3 = *(const float4*)(vbase + (k4*4+3)*256);
            #pragma unroll
            for (int i = 0; i < 16; ++i) {
                float4 pw = *(const float4*)&sc[(qg*16+i)*64 + k4*4];
                acc[i][0] += pw.x*v0.x; acc[i][1] += pw.x*v0.y; acc[i][2] += pw.x*v0.z; acc[i][3] += pw.x*v0.w;
                acc[i][0] += pw.y*v1.x; acc[i][1] += pw.y*v1.y; acc[i][2] += pw.y*v1.z; acc[i][3] += pw.y*v1.w;
                acc[i][0] += pw.z*v2.x; acc[i][1] += pw.z*v2.y; acc[i][2] += pw.z*v2.z; acc[i][3] += pw.z*v2.w;
                acc[i][0] += pw.w*v3.x; acc[i][1] += pw.w*v3.y; acc[i][2] += pw.w*v3.z; acc[i][3] += pw.w*v3.w;
            }
        }
    }

    // ---- epilogue ----
    #pragma unroll
    for (int i = 0; i < 16; ++i) {
        int q = qg*16 + i;
        float il = 1.f / lsm[q];
        float4 o;
        o.x = acc[i][0]*il; o.y = acc[i][1]*il; o.z = acc[i][2]*il; o.w = acc[i][3]*il;
        *(float4*)&g_cat[(size_t)(b*SEQ + n0 + q)*1024 + head*HDIM + hh*128 + lane*4] = o;
    }
}

// ---------------- host launch ----------------
extern "C" void kernel_launch(void* const* d_in, const int* in_sizes, int n_in,
                              void* d_out, int out_size)
{
    const float* Q        = (const float*)d_in[0];
    const float* K        = (const float*)d_in[1];
    const float* V        = (const float*)d_in[2];
    const float* bq_w     = (const float*)d_in[3];
    const float* bq_b     = (const float*)d_in[4];
    const float* bk_w     = (const float*)d_in[5];
    const float* bk_b     = (const float*)d_in[6];
    const float* b_v      = (const float*)d_in[7];
    const float* tq_w     = (const float*)d_in[8];
    const float* tq_b     = (const float*)d_in[9];
    const float* tk_w     = (const float*)d_in[10];
    const float* tk_b     = (const float*)d_in[11];
    const float* t_v      = (const float*)d_in[12];
    const float* t_temp   = (const float*)d_in[13];
    const float* rq_w     = (const float*)d_in[14];
    const float* rq_b     = (const float*)d_in[15];
    const float* rk_w     = (const float*)d_in[16];
    const float* rk_b     = (const float*)d_in[17];
    const float* r_v      = (const float*)d_in[18];
    const float* pq_w     = (const float*)d_in[19];
    const float* pq_b     = (const float*)d_in[20];
    const float* pk_w     = (const float*)d_in[21];
    const float* pk_b     = (const float*)d_in[22];
    const float* p_v      = (const float*)d_in[23];
    const float* p_fusion = (const float*)d_in[24];
    const float* out_w    = (const float*)d_in[25];
    const float* out_b    = (const float*)d_in[26];
    float* out = (float*)d_out;

    void *pWq, *pWk, *pBq, *pBk, *pWv, *pqp, *pkp, *pVp, *pcat;
    cudaGetSymbolAddress(&pWq,  g_Wq);
    cudaGetSymbolAddress(&pWk,  g_Wk);
    cudaGetSymbolAddress(&pBq,  g_Bq);
    cudaGetSymbolAddress(&pBk,  g_Bk);
    cudaGetSymbolAddress(&pWv,  g_Wv);
    cudaGetSymbolAddress(&pqp,  g_qproj);
    cudaGetSymbolAddress(&pkp,  g_kproj);
    cudaGetSymbolAddress(&pVp,  g_Vp);
    cudaGetSymbolAddress(&pcat, g_cat);

    pack_weights<<<256, 256>>>(bq_w, tq_w, rq_w, pq_w, bq_b, tq_b, rq_b, pq_b,
                               bk_w, tk_w, rk_w, pk_w, bk_b, tk_b, rk_b, pk_b,
                               b_v, t_v, r_v, p_v);

    // Q/K projections fused in one launch: [2048 x 192 x 1024], z selects Q/K
    gemm_db<64,4><<<dim3(2, 32, 2), 256>>>(
        Q, K, (const float*)pWq, (const float*)pWk,
        (const float*)pBq, (const float*)pBk,
        (float*)pqp, (float*)pkp, NTOK, PROJ, DIM);

    // V projection: [2048 x 1024 x 1024]
    gemm_db<128,8><<<dim3(8, 16, 1), 256>>>(
        V, V, (const float*)pWv, (const float*)pWv,
        nullptr, nullptr, (float*)pVp, (float*)pVp, NTOK, 4*HDIM, DIM);

    pack_bits<<<NTOK*32/256, 256>>>();

    cudaFuncSetAttribute(attn_kernel, cudaFuncAttributeMaxDynamicSharedMemorySize,
                         ATTN_SMEM_BYTES);
    attn_kernel<<<dim3(SEQ/64, BATCH, 4), 256, ATTN_SMEM_BYTES>>>(t_temp, p_fusion);

    // output projection: [2048 x 1024 x 1024]
    gemm_db<128,8><<<dim3(8, 16, 1), 256>>>(
        (const float*)pcat, (const float*)pcat, out_w, out_w,
        out_b, out_b, out, out, NTOK, DIM, DIM);
}

// round 3
// speedup vs baseline: 2.2311x; 1.3284x over previous
#include <cuda_runtime.h>
#include <math.h>

// ---------------- problem constants ----------------
#define BATCH 2
#define SEQ   1024
#define DIM   1024
#define HDIM  256
#define MBITS 32
#define NTOK  (BATCH*SEQ)     // 2048
#define PROJ  192             // 6 groups x 32
#define SCALEF 0.17677669529663687f  // 1/sqrt(32)

// ---------------- device scratch (static, no allocs) ----------------
__device__ float    g_Wq[PROJ*DIM];
__device__ float    g_Wk[PROJ*DIM];
__device__ float    g_Bq[PROJ];
__device__ float    g_Bk[PROJ];
__device__ float    g_Wv[4*HDIM*DIM];
__device__ float    g_qproj[NTOK*PROJ];
__device__ float    g_kproj[NTOK*PROJ];
__device__ unsigned g_qbits[NTOK*2];
__device__ unsigned g_kbits[NTOK*2];
__device__ float    g_Vp[NTOK*4*HDIM];
__device__ float    g_cat[NTOK*4*HDIM];

// ---------------- pack weights into fused layouts ----------------
__global__ void pack_weights(
    const float* __restrict__ bq_w, const float* __restrict__ tq_w,
    const float* __restrict__ rq_w, const float* __restrict__ pq_w,
    const float* __restrict__ bq_b, const float* __restrict__ tq_b,
    const float* __restrict__ rq_b, const float* __restrict__ pq_b,
    const float* __restrict__ bk_w, const float* __restrict__ tk_w,
    const float* __restrict__ rk_w, const float* __restrict__ pk_w,
    const float* __restrict__ bk_b, const float* __restrict__ tk_b,
    const float* __restrict__ rk_b, const float* __restrict__ pk_b,
    const float* __restrict__ b_v,  const float* __restrict__ t_v,
    const float* __restrict__ r_v,  const float* __restrict__ p_v)
{
    int i0 = blockIdx.x * blockDim.x + threadIdx.x;
    int stride = gridDim.x * blockDim.x;
    for (int e = i0; e < 4*HDIM*DIM; e += stride) {
        int h = e >> 10, d = e & 1023;
        float v;
        if (h < 256)      v = b_v[h*DIM + d];
        else if (h < 512) v = t_v[(h-256)*DIM + d];
        else if (h < 768) v = r_v[(h-512)*DIM + d];
        else              v = p_v[(h-768)*DIM + d];
        g_Wv[e] = v;
    }
    for (int e = i0; e < PROJ*DIM; e += stride) {
        int r = e >> 10, d = e & 1023;
        int g = r >> 5, j = r & 31;
        const float* sq; const float* sk;
        switch (g) {
            case 0: sq = bq_w; sk = bk_w; break;
            case 1: sq = tq_w; sk = tk_w; break;
            case 2: sq = rq_w; sk = rk_w; break;
            default: sq = pq_w + (g-3)*MBITS*DIM; sk = pk_w + (g-3)*MBITS*DIM; break;
        }
        int off = j*DIM + d;
        g_Wq[e] = sq[off];
        g_Wk[e] = sk[off];
    }
    for (int e = i0; e < PROJ; e += stride) {
        int g = e >> 5, j = e & 31;
        float vq, vk;
        switch (g) {
            case 0: vq = bq_b[j]; vk = bk_b[j]; break;
            case 1: vq = tq_b[j]; vk = tk_b[j]; break;
            case 2: vq = rq_b[j]; vk = rk_b[j]; break;
            default: vq = pq_b[(g-3)*MBITS + j]; vk = pk_b[(g-3)*MBITS + j]; break;
        }
        g_Bq[e] = vq;
        g_Bk[e] = vk;
    }
}

// ---------------- fp32 double-buffered GEMM (used for exact QK projections) ----
template<int BM, int TM>
__global__ __launch_bounds__(256) void gemm_db(
    const float* __restrict__ A0, const float* __restrict__ A1,
    const float* __restrict__ W0, const float* __restrict__ W1,
    const float* __restrict__ b0, const float* __restrict__ b1,
    float* __restrict__ C0, float* __restrict__ C1,
    int M, int N, int K)
{
    __shared__ __align__(16) float As[2][8][BM+4];
    __shared__ __align__(16) float Ws[2][8][132];

    const float* A    = blockIdx.z ? A1 : A0;
    const float* W    = blockIdx.z ? W1 : W0;
    const float* bias = blockIdx.z ? b1 : b0;
    float*       C    = blockIdx.z ? C1 : C0;

    const int bm = blockIdx.y * BM, bn = blockIdx.x * 128;
    const int tid = threadIdx.x;
    const int tx = tid & 15, ty = tid >> 4;
    const int lrow = tid >> 1, lc4 = (tid & 1) * 4;

    const bool aact = (tid < BM*2);
    const bool wact = (bn + lrow) < N;
    const float* Aptr = A + (size_t)(bm + lrow)*K + lc4;
    const float* Wptr = W + (size_t)(bn + lrow)*K + lc4;

    float acc[TM][8];
    #pragma unroll
    for (int i = 0; i < TM; ++i)
        #pragma unroll
        for (int j = 0; j < 8; ++j) acc[i][j] = 0.f;

    const int nt = K >> 3;
    float4 areg = make_float4(0,0,0,0), wreg = make_float4(0,0,0,0);
    if (aact) areg = *(const float4*)Aptr;
    if (wact) wreg = *(const float4*)Wptr;
    #pragma unroll
    for (int j = 0; j < 4; ++j) {
        if (aact) As[0][lc4+j][lrow] = (&areg.x)[j];
        Ws[0][lc4+j][lrow] = (&wreg.x)[j];
    }
    __syncthreads();

    for (int t = 0; t < nt; ++t) {
        const int cur = t & 1;
        if (t + 1 < nt) {
            if (aact) areg = *(const float4*)(Aptr + (t+1)*8);
            if (wact) wreg = *(const float4*)(Wptr + (t+1)*8);
        }
        #pragma unroll
        for (int kk = 0; kk < 8; ++kk) {
            float a[TM], b[8];
            *(float4*)&b[0] = *(const float4*)&Ws[cur][kk][tx*8];
            *(float4*)&b[4] = *(const float4*)&Ws[cur][kk][tx*8+4];
            *(float4*)&a[0] = *(const float4*)&As[cur][kk][ty*TM];
            if (TM == 8) *(float4*)&a[4] = *(const float4*)&As[cur][kk][ty*TM+4];
            #pragma unroll
            for (int i = 0; i < TM; ++i)
                #pragma unroll
                for (int j = 0; j < 8; ++j)
                    acc[i][j] += a[i]*b[j];
        }
        if (t + 1 < nt) {
            const int nxt = cur ^ 1;
            #pragma unroll
            for (int j = 0; j < 4; ++j) {
                if (aact) As[nxt][lc4+j][lrow] = (&areg.x)[j];
                Ws[nxt][lc4+j][lrow] = (&wreg.x)[j];
            }
        }
        __syncthreads();
    }

    #pragma unroll
    for (int i = 0; i < TM; ++i) {
        int row = bm + ty*TM + i;
        #pragma unroll
        for (int j4 = 0; j4 < 2; ++j4) {
            int col = bn + tx*8 + j4*4;
            if (col < N) {
                float4 o;
                o.x = acc[i][j4*4+0]; o.y = acc[i][j4*4+1];
                o.z = acc[i][j4*4+2]; o.w = acc[i][j4*4+3];
                if (bias) { o.x += bias[col]; o.y += bias[col+1]; o.z += bias[col+2]; o.w += bias[col+3]; }
                *(float4*)&C[(size_t)row*N + col] = o;
            }
        }
    }
}

// ---------------- tf32 tensor-core GEMM (V-proj, out-proj) ----------------
// C[M,N] = A[M,K]*W[N,K]^T + bias.  128x128 block, BK=8 double-buffered,
// 8 warps, each warp 64x32 via mma.sync.m16n8k8 tf32. M,N,K multiples of 128.
__device__ __forceinline__ unsigned f2tf32(float f) {
    unsigned u;
    asm("cvt.rna.tf32.f32 %0, %1;" : "=r"(u) : "f"(f));
    return u;
}
__device__ __forceinline__ void mma_tf32(float c[4],
    unsigned a0, unsigned a1, unsigned a2, unsigned a3,
    unsigned b0, unsigned b1)
{
    asm("mma.sync.aligned.m16n8k8.row.col.f32.tf32.tf32.f32 "
        "{%0,%1,%2,%3},{%4,%5,%6,%7},{%8,%9},{%0,%1,%2,%3};"
        : "+f"(c[0]), "+f"(c[1]), "+f"(c[2]), "+f"(c[3])
        : "r"(a0), "r"(a1), "r"(a2), "r"(a3), "r"(b0), "r"(b1));
}

__global__ __launch_bounds__(256) void gemm_tc(
    const float* __restrict__ A, const float* __restrict__ W,
    const float* __restrict__ bias, float* __restrict__ C,
    int M, int N, int K)
{
    __shared__ unsigned As[2][8][136];
    __shared__ unsigned Ws[2][8][136];

    const int bm = blockIdx.y * 128, bn = blockIdx.x * 128;
    const int tid = threadIdx.x;
    const int w = tid >> 5, lane = tid & 31;
    const int wm = w >> 2, wn = w & 3;       // warp grid 2x4 -> 64x32 per warp
    const int qr = lane >> 2, qc = lane & 3;
    const int lrow = tid >> 1, lc4 = (tid & 1) * 4;

    const float* Aptr = A + (size_t)(bm + lrow)*K + lc4;
    const float* Wptr = W + (size_t)(bn + lrow)*K + lc4;

    float acc[4][4][4];
    #pragma unroll
    for (int i = 0; i < 4; ++i)
        #pragma unroll
        for (int j = 0; j < 4; ++j)
            #pragma unroll
            for (int r = 0; r < 4; ++r) acc[i][j][r] = 0.f;

    const int nt = K >> 3;
    float4 areg = *(const float4*)Aptr;
    float4 wreg = *(const float4*)Wptr;
    #pragma unroll
    for (int j = 0; j < 4; ++j) {
        As[0][lc4+j][lrow] = f2tf32((&areg.x)[j]);
        Ws[0][lc4+j][lrow] = f2tf32((&wreg.x)[j]);
    }
    __syncthreads();

    for (int t = 0; t < nt; ++t) {
        const int cur = t & 1;
        if (t + 1 < nt) {
            areg = *(const float4*)(Aptr + (t+1)*8);
            wreg = *(const float4*)(Wptr + (t+1)*8);
        }
        unsigned af[4][4], bf[4][2];
        #pragma unroll
        for (int i = 0; i < 4; ++i) {
            int m0 = wm*64 + i*16 + qr;
            af[i][0] = As[cur][qc  ][m0];
            af[i][1] = As[cur][qc  ][m0+8];
            af[i][2] = As[cur][qc+4][m0];
            af[i][3] = As[cur][qc+4][m0+8];
        }
        #pragma unroll
        for (int j = 0; j < 4; ++j) {
            int n0 = wn*32 + j*8 + qr;
            bf[j][0] = Ws[cur][qc  ][n0];
            bf[j][1] = Ws[cur][qc+4][n0];
        }
        #pragma unroll
        for (int i = 0; i < 4; ++i)
            #pragma unroll
            for (int j = 0; j < 4; ++j)
                mma_tf32(acc[i][j], af[i][0], af[i][1], af[i][2], af[i][3],
                         bf[j][0], bf[j][1]);
        if (t + 1 < nt) {
            const int nxt = cur ^ 1;
            #pragma unroll
            for (int j = 0; j < 4; ++j) {
                As[nxt][lc4+j][lrow] = f2tf32((&areg.x)[j]);
                Ws[nxt][lc4+j][lrow] = f2tf32((&wreg.x)[j]);
            }
        }
        __syncthreads();
    }

    #pragma unroll
    for (int i = 0; i < 4; ++i) {
        int r0 = bm + wm*64 + i*16 + qr;
        #pragma unroll
        for (int j = 0; j < 4; ++j) {
            int c0 = bn + wn*32 + j*8 + 2*qc;
            float bx = 0.f, by = 0.f;
            if (bias) { bx = bias[c0]; by = bias[c0+1]; }
            float2 o0, o1;
            o0.x = acc[i][j][0] + bx; o0.y = acc[i][j][1] + by;
            o1.x = acc[i][j][2] + bx; o1.y = acc[i][j][3] + by;
            *(float2*)&C[(size_t)r0*N + c0]     = o0;
            *(float2*)&C[(size_t)(r0+8)*N + c0] = o1;
        }
    }
}

// ---------------- bit packing for boolean heads ----------------
__global__ void pack_bits()
{
    int gw = (blockIdx.x * blockDim.x + threadIdx.x) >> 5;
    int lane = threadIdx.x & 31;
    if (gw >= NTOK) return;
    unsigned q0 = __ballot_sync(0xffffffffu, g_qproj[(size_t)gw*PROJ + lane]       > 0.f);
    unsigned q1 = __ballot_sync(0xffffffffu, g_qproj[(size_t)gw*PROJ + 96 + lane]  > 0.f);
    unsigned k0 = __ballot_sync(0xffffffffu, g_kproj[(size_t)gw*PROJ + lane]       > 0.f);
    unsigned k1 = __ballot_sync(0xffffffffu, g_kproj[(size_t)gw*PROJ + 96 + lane]  > 0.f);
    if (lane == 0) {
        g_qbits[gw*2]   = q0; g_qbits[gw*2+1] = q1;
        g_kbits[gw*2]   = k0; g_kbits[gw*2+1] = k1;
    }
}

// ---------------- fused attention: 64 queries x 1 head per block ----------------
__device__ __forceinline__ float wredmax(float v) {
    #pragma unroll
    for (int o = 16; o; o >>= 1) v = fmaxf(v, __shfl_xor_sync(0xffffffffu, v, o));
    return v;
}
__device__ __forceinline__ float wredsum(float v) {
    #pragma unroll
    for (int o = 16; o; o >>= 1) v += __shfl_xor_sync(0xffffffffu, v, o);
    return v;
}

#define ATTN_SMEM_FLOATS (16384 + 4096 + 4*2112 + 3*64 + 128)
#define ATTN_SMEM_BYTES  (ATTN_SMEM_FLOATS*4)

__global__ __launch_bounds__(256) void attn_kernel(const float* __restrict__ t_temp,
                                                   const float* __restrict__ p_fusion)
{
    extern __shared__ __align__(16) float sm[];
    float* vp  = sm;                  // [64][256]
    float* sc  = vp + 16384;          // [64][64]
    float* qe0 = sc + 4096;           // [64][33]
    float* qe1 = qe0 + 2112;
    float* ke0 = qe1 + 2112;          // [64][33]
    float* ke1 = ke0 + 2112;
    float* msm = ke1 + 2112;          // [64]
    float* lsm = msm + 64;
    float* cf  = lsm + 64;
    unsigned* qb = (unsigned*)(cf + 64);   // [64]
    unsigned* kb = qb + 64;                // [64]

    const int n0   = blockIdx.x * 64;
    const int b    = blockIdx.y;
    const int head = blockIdx.z;
    const int tid  = threadIdx.x;
    const int lane = tid & 31;
    const int w    = tid >> 5;

    float inv_sp = 1.f;
    if (head == 1) inv_sp = 1.f / log1pf(expf(t_temp[0]));
    float fw0 = 0.f, fw1 = 0.f, fw2 = 0.f;
    if (head == 3) {
        float p0 = p_fusion[0], p1 = p_fusion[1], p2 = p_fusion[2];
        float mx = fmaxf(p0, fmaxf(p1, p2));
        float e0 = expf(p0-mx), e1 = expf(p1-mx), e2 = expf(p2-mx);
        float inv = 1.f/(e0+e1+e2);
        fw0 = e0*inv; fw1 = e1*inv; fw2 = e2*inv;
    }

    if (tid < 64) { msm[tid] = -INFINITY; lsm[tid] = 0.f; }

    if (head == 0) {
        if (tid < 64) qb[tid] = g_qbits[(b*SEQ + n0 + tid)*2 + 0];
    } else if (head == 3) {
        if (tid < 64) qb[tid] = g_qbits[(b*SEQ + n0 + tid)*2 + 1];
        for (int j = tid; j < 2048; j += 256) {
            int t = j >> 5, m = j & 31;
            const float* base = &g_qproj[(size_t)(b*SEQ + n0 + t)*PROJ];
            qe0[t*33+m] = base[128+m];
            qe1[t*33+m] = base[160+m];
        }
    } else {
        int off = (head == 1) ? 32 : 64;
        for (int j = tid; j < 2048; j += 256) {
            int t = j >> 5, m = j & 31;
            qe0[t*33+m] = g_qproj[(size_t)(b*SEQ + n0 + t)*PROJ + off + m];
        }
    }

    const int qg = w >> 1;
    const int hh = w & 1;
    float acc[16][4];
    #pragma unroll
    for (int i = 0; i < 16; ++i)
        #pragma unroll
        for (int j = 0; j < 4; ++j) acc[i][j] = 0.f;

    const float* vp_g = &g_Vp[(size_t)(b*SEQ)*1024 + head*HDIM];
    const int kk  = tid & 63;
    const int qb4 = tid >> 6;

    for (int k0i = 0; k0i < SEQ; k0i += 64) {
        __syncthreads();

        #pragma unroll
        for (int i = 0; i < 16; ++i) {
            int idx = tid + 256*i;
            int row = idx >> 6, c4 = idx & 63;
            ((float4*)vp)[idx] = *(const float4*)&vp_g[(size_t)(k0i+row)*1024 + c4*4];
        }
        if (head == 0) {
            if (tid < 64) kb[tid] = g_kbits[(b*SEQ + k0i + tid)*2 + 0];
        } else if (head == 3) {
            if (tid < 64) kb[tid] = g_kbits[(b*SEQ + k0i + tid)*2 + 1];
            for (int j = tid; j < 2048; j += 256) {
                int t = j >> 5, m = j & 31;
                const float* base = &g_kproj[(size_t)(b*SEQ + k0i + t)*PROJ];
                ke0[t*33+m] = base[128+m];
                ke1[t*33+m] = base[160+m];
            }
        } else {
            int off = (head == 1) ? 32 : 64;
            for (int j = tid; j < 2048; j += 256) {
                int t = j >> 5, m = j & 31;
                ke0[t*33+m] = g_kproj[(size_t)(b*SEQ + k0i + t)*PROJ + off + m];
            }
        }
        __syncthreads();

        if (head == 0) {
            unsigned kr = kb[kk];
            #pragma unroll
            for (int i = 0; i < 16; ++i) {
                int q = qb4*16 + i;
                int p = __popc(qb[q] ^ kr);
                sc[q*64 + kk] = (1.f - p*(1.f/32.f)) * SCALEF;
            }
        } else if (head == 1) {
            float kr[32];
            #pragma unroll
            for (int m = 0; m < 32; ++m) kr[m] = ke0[kk*33+m];
            #pragma unroll 4
            for (int i = 0; i < 16; ++i) {
                int q = qb4*16 + i;
                const float* qe = &qe0[q*33];
                float mna = INFINITY, mnb = INFINITY;
                #pragma unroll
                for (int m = 0; m < 32; m += 2) {
                    mna = fminf(mna, qe[m]   + kr[m]);
                    mnb = fminf(mnb, qe[m+1] + kr[m+1]);
                }
                sc[q*64 + kk] = -fminf(mna, mnb) * inv_sp;
            }
        } else if (head == 2) {
            float kr[32];
            #pragma unroll
            for (int m = 0; m < 32; ++m) kr[m] = ke0[kk*33+m];
            #pragma unroll 4
            for (int i = 0; i < 16; ++i) {
                int q = qb4*16 + i;
                const float* qe = &qe0[q*33];
                float da = 0.f, db = 0.f;
                #pragma unroll
                for (int m = 0; m < 32; m += 2) {
                    da = fmaf(qe[m],   kr[m],   da);
                    db = fmaf(qe[m+1], kr[m+1], db);
                }
                sc[q*64 + kk] = (da + db) * SCALEF;
            }
        } else {
            float kr0[32], kr1[32];
            #pragma unroll
            for (int m = 0; m < 32; ++m) { kr0[m] = ke0[kk*33+m]; kr1[m] = ke1[kk*33+m]; }
            unsigned kr = kb[kk];
            #pragma unroll 2
            for (int i = 0; i < 16; ++i) {
                int q = qb4*16 + i;
                const float* qe_t = &qe0[q*33];
                const float* qe_r = &qe1[q*33];
                float simb = 1.f - __popc(qb[q] ^ kr)*(1.f/32.f);
                float mna = INFINITY, mnb = INFINITY;
                float da = 0.f, db = 0.f;
                #pragma unroll
                for (int m = 0; m < 32; m += 2) {
                    mna = fminf(mna, qe_t[m]   + kr0[m]);
                    mnb = fminf(mnb, qe_t[m+1] + kr0[m+1]);
                    da = fmaf(qe_r[m],   kr1[m],   da);
                    db = fmaf(qe_r[m+1], kr1[m+1], db);
                }
                sc[q*64 + kk] = (fw0*simb - fw1*fminf(mna,mnb) + fw2*(da+db)) * SCALEF;
            }
        }
        __syncthreads();

        #pragma unroll
        for (int j = 0; j < 8; ++j) {
            int q = w*8 + j;
            float s0 = sc[q*64 + lane], s1 = sc[q*64 + lane + 32];
            float tm = wredmax(fmaxf(s0, s1));
            float mold = msm[q];
            float mnew = fmaxf(mold, tm);
            float c  = __expf(mold - mnew);
            float p0 = __expf(s0 - mnew), p1 = __expf(s1 - mnew);
            sc[q*64 + lane] = p0; sc[q*64 + lane + 32] = p1;
            float ls = wredsum(p0 + p1);
            if (lane == 0) { msm[q] = mnew; lsm[q] = lsm[q]*c + ls; cf[q] = c; }
        }
        __syncthreads();

        #pragma unroll
        for (int i = 0; i < 16; ++i) {
            float c = cf[qg*16 + i];
            #pragma unroll
            for (int j = 0; j < 4; ++j) acc[i][j] *= c;
        }
        const float* vbase = vp + hh*128 + lane*4;
        #pragma unroll 4
        for (int k4 = 0; k4 < 16; ++k4) {
            float4 v0 = *(const float4*)(vbase + (k4*4+0)*256);
            float4 v1 = *(const float4*)(vbase + (k4*4+1)*256);
            float4 v2 = *(const float4*)(vbase + (k4*4+2)*256);
            float4 v3 = *(const float4*)(vbase + (k4*4+3)*256);
            #pragma unroll
            for (int i = 0; i < 16; ++i) {
                float4 pw = *(const float4*)&sc[(qg*16+i)*64 + k4*4];
                acc[i][0] += pw.x*v0.x; acc[i][1] += pw.x*v0.y; acc[i][2] += pw.x*v0.z; acc[i][3] += pw.x*v0.w;
                acc[i][0] += pw.y*v1.x; acc[i][1] += pw.y*v1.y; acc[i][2] += pw.y*v1.z; acc[i][3] += pw.y*v1.w;
                acc[i][0] += pw.z*v2.x; acc[i][1] += pw.z*v2.y; acc[i][2] += pw.z*v2.z; acc[i][3] += pw.z*v2.w;
                acc[i][0] += pw.w*v3.x; acc[i][1] += pw.w*v3.y; acc[i][2] += pw.w*v3.z; acc[i][3] += pw.w*v3.w;
            }
        }
    }

    #pragma unroll
    for (int i = 0; i < 16; ++i) {
        int q = qg*16 + i;
        float il = 1.f / lsm[q];
        float4 o;
        o.x = acc[i][0]*il; o.y = acc[i][1]*il; o.z = acc[i][2]*il; o.w = acc[i][3]*il;
        *(float4*)&g_cat[(size_t)(b*SEQ + n0 + q)*1024 + head*HDIM + hh*128 + lane*4] = o;
    }
}

// ---------------- host launch ----------------
extern "C" void kernel_launch(void* const* d_in, const int* in_sizes, int n_in,
                              void* d_out, int out_size)
{
    const float* Q        = (const float*)d_in[0];
    const float* K        = (const float*)d_in[1];
    const float* V        = (const float*)d_in[2];
    const float* bq_w     = (const float*)d_in[3];
    const float* bq_b     = (const float*)d_in[4];
    const float* bk_w     = (const float*)d_in[5];
    const float* bk_b     = (const float*)d_in[6];
    const float* b_v      = (const float*)d_in[7];
    const float* tq_w     = (const float*)d_in[8];
    const float* tq_b     = (const float*)d_in[9];
    const float* tk_w     = (const float*)d_in[10];
    const float* tk_b     = (const float*)d_in[11];
    const float* t_v      = (const float*)d_in[12];
    const float* t_temp   = (const float*)d_in[13];
    const float* rq_w     = (const float*)d_in[14];
    const float* rq_b     = (const float*)d_in[15];
    const float* rk_w     = (const float*)d_in[16];
    const float* rk_b     = (const float*)d_in[17];
    const float* r_v      = (const float*)d_in[18];
    const float* pq_w     = (const float*)d_in[19];
    const float* pq_b     = (const float*)d_in[20];
    const float* pk_w     = (const float*)d_in[21];
    const float* pk_b     = (const float*)d_in[22];
    const float* p_v      = (const float*)d_in[23];
    const float* p_fusion = (const float*)d_in[24];
    const float* out_w    = (const float*)d_in[25];
    const float* out_b    = (const float*)d_in[26];
    float* out = (float*)d_out;

    void *pWq, *pWk, *pBq, *pBk, *pWv, *pqp, *pkp, *pVp, *pcat;
    cudaGetSymbolAddress(&pWq,  g_Wq);
    cudaGetSymbolAddress(&pWk,  g_Wk);
    cudaGetSymbolAddress(&pBq,  g_Bq);
    cudaGetSymbolAddress(&pBk,  g_Bk);
    cudaGetSymbolAddress(&pWv,  g_Wv);
    cudaGetSymbolAddress(&pqp,  g_qproj);
    cudaGetSymbolAddress(&pkp,  g_kproj);
    cudaGetSymbolAddress(&pVp,  g_Vp);
    cudaGetSymbolAddress(&pcat, g_cat);

    pack_weights<<<256, 256>>>(bq_w, tq_w, rq_w, pq_w, bq_b, tq_b, rq_b, pq_b,
                               bk_w, tk_w, rk_w, pk_w, bk_b, tk_b, rk_b, pk_b,
                               b_v, t_v, r_v, p_v);

    // Q/K projections (exact fp32): [2048 x 192 x 1024], z selects Q/K
    gemm_db<64,4><<<dim3(2, 32, 2), 256>>>(
        Q, K, (const float*)pWq, (const float*)pWk,
        (const float*)pBq, (const float*)pBk,
        (float*)pqp, (float*)pkp, NTOK, PROJ, DIM);

    // V projection (tf32 tensor cores): [2048 x 1024 x 1024]
    gemm_tc<<<dim3(8, 16), 256>>>(V, (const float*)pWv, nullptr,
                                  (float*)pVp, NTOK, 4*HDIM, DIM);

    pack_bits<<<NTOK*32/256, 256>>>();

    cudaFuncSetAttribute(attn_kernel, cudaFuncAttributeMaxDynamicSharedMemorySize,
                         ATTN_SMEM_BYTES);
    attn_kernel<<<dim3(SEQ/64, BATCH, 4), 256, ATTN_SMEM_BYTES>>>(t_temp, p_fusion);

    // output projection (tf32 tensor cores): [2048 x 1024 x 1024]
    gemm_tc<<<dim3(8, 16), 256>>>((const float*)pcat, out_w, out_b,
                                  out, NTOK, DIM, DIM);
}

// round 4
// speedup vs baseline: 2.6002x; 1.1654x over previous
#include <cuda_runtime.h>
#include <math.h>

// ---------------- problem constants ----------------
#define BATCH 2
#define SEQ   1024
#define DIM   1024
#define HDIM  256
#define MBITS 32
#define NTOK  (BATCH*SEQ)     // 2048
#define PROJ  192             // 6 groups x 32
#define SCALEF 0.17677669529663687f  // 1/sqrt(32)

// ---------------- device scratch (static, no allocs) ----------------
__device__ float    g_Wq[PROJ*DIM];
__device__ float    g_Wk[PROJ*DIM];
__device__ float    g_Bq[PROJ];
__device__ float    g_Bk[PROJ];
__device__ float    g_Wv[4*HDIM*DIM];
__device__ float    g_qproj[NTOK*PROJ];
__device__ float    g_kproj[NTOK*PROJ];
__device__ unsigned g_qbits[NTOK*2];
__device__ unsigned g_kbits[NTOK*2];
__device__ float    g_Vp[NTOK*4*HDIM];
__device__ float    g_cat[NTOK*4*HDIM];

// ---------------- pack weights into fused layouts ----------------
__global__ void pack_weights(
    const float* __restrict__ bq_w, const float* __restrict__ tq_w,
    const float* __restrict__ rq_w, const float* __restrict__ pq_w,
    const float* __restrict__ bq_b, const float* __restrict__ tq_b,
    const float* __restrict__ rq_b, const float* __restrict__ pq_b,
    const float* __restrict__ bk_w, const float* __restrict__ tk_w,
    const float* __restrict__ rk_w, const float* __restrict__ pk_w,
    const float* __restrict__ bk_b, const float* __restrict__ tk_b,
    const float* __restrict__ rk_b, const float* __restrict__ pk_b,
    const float* __restrict__ b_v,  const float* __restrict__ t_v,
    const float* __restrict__ r_v,  const float* __restrict__ p_v)
{
    int i0 = blockIdx.x * blockDim.x + threadIdx.x;
    int stride = gridDim.x * blockDim.x;
    for (int e = i0; e < 4*HDIM*DIM; e += stride) {
        int h = e >> 10, d = e & 1023;
        float v;
        if (h < 256)      v = b_v[h*DIM + d];
        else if (h < 512) v = t_v[(h-256)*DIM + d];
        else if (h < 768) v = r_v[(h-512)*DIM + d];
        else              v = p_v[(h-768)*DIM + d];
        g_Wv[e] = v;
    }
    for (int e = i0; e < PROJ*DIM; e += stride) {
        int r = e >> 10, d = e & 1023;
        int g = r >> 5, j = r & 31;
        const float* sq; const float* sk;
        switch (g) {
            case 0: sq = bq_w; sk = bk_w; break;
            case 1: sq = tq_w; sk = tk_w; break;
            case 2: sq = rq_w; sk = rk_w; break;
            default: sq = pq_w + (g-3)*MBITS*DIM; sk = pk_w + (g-3)*MBITS*DIM; break;
        }
        int off = j*DIM + d;
        g_Wq[e] = sq[off];
        g_Wk[e] = sk[off];
    }
    for (int e = i0; e < PROJ; e += stride) {
        int g = e >> 5, j = e & 31;
        float vq, vk;
        switch (g) {
            case 0: vq = bq_b[j]; vk = bk_b[j]; break;
            case 1: vq = tq_b[j]; vk = tk_b[j]; break;
            case 2: vq = rq_b[j]; vk = rk_b[j]; break;
            default: vq = pq_b[(g-3)*MBITS + j]; vk = pk_b[(g-3)*MBITS + j]; break;
        }
        g_Bq[e] = vq;
        g_Bk[e] = vk;
    }
}

// ---------------- fp32 double-buffered GEMM (exact QK projections) ----------
template<int BM, int TM>
__global__ __launch_bounds__(256) void gemm_db(
    const float* __restrict__ A0, const float* __restrict__ A1,
    const float* __restrict__ W0, const float* __restrict__ W1,
    const float* __restrict__ b0, const float* __restrict__ b1,
    float* __restrict__ C0, float* __restrict__ C1,
    int M, int N, int K)
{
    __shared__ __align__(16) float As[2][8][BM+4];
    __shared__ __align__(16) float Ws[2][8][132];

    const float* A    = blockIdx.z ? A1 : A0;
    const float* W    = blockIdx.z ? W1 : W0;
    const float* bias = blockIdx.z ? b1 : b0;
    float*       C    = blockIdx.z ? C1 : C0;

    const int bm = blockIdx.y * BM, bn = blockIdx.x * 128;
    const int tid = threadIdx.x;
    const int tx = tid & 15, ty = tid >> 4;
    const int lrow = tid >> 1, lc4 = (tid & 1) * 4;

    const bool aact = (tid < BM*2);
    const bool wact = (bn + lrow) < N;
    const float* Aptr = A + (size_t)(bm + lrow)*K + lc4;
    const float* Wptr = W + (size_t)(bn + lrow)*K + lc4;

    float acc[TM][8];
    #pragma unroll
    for (int i = 0; i < TM; ++i)
        #pragma unroll
        for (int j = 0; j < 8; ++j) acc[i][j] = 0.f;

    const int nt = K >> 3;
    float4 areg = make_float4(0,0,0,0), wreg = make_float4(0,0,0,0);
    if (aact) areg = *(const float4*)Aptr;
    if (wact) wreg = *(const float4*)Wptr;
    #pragma unroll
    for (int j = 0; j < 4; ++j) {
        if (aact) As[0][lc4+j][lrow] = (&areg.x)[j];
        Ws[0][lc4+j][lrow] = (&wreg.x)[j];
    }
    __syncthreads();

    for (int t = 0; t < nt; ++t) {
        const int cur = t & 1;
        if (t + 1 < nt) {
            if (aact) areg = *(const float4*)(Aptr + (t+1)*8);
            if (wact) wreg = *(const float4*)(Wptr + (t+1)*8);
        }
        #pragma unroll
        for (int kk = 0; kk < 8; ++kk) {
            float a[TM], b[8];
            *(float4*)&b[0] = *(const float4*)&Ws[cur][kk][tx*8];
            *(float4*)&b[4] = *(const float4*)&Ws[cur][kk][tx*8+4];
            *(float4*)&a[0] = *(const float4*)&As[cur][kk][ty*TM];
            if (TM == 8) *(float4*)&a[4] = *(const float4*)&As[cur][kk][ty*TM+4];
            #pragma unroll
            for (int i = 0; i < TM; ++i)
                #pragma unroll
                for (int j = 0; j < 8; ++j)
                    acc[i][j] += a[i]*b[j];
        }
        if (t + 1 < nt) {
            const int nxt = cur ^ 1;
            #pragma unroll
            for (int j = 0; j < 4; ++j) {
                if (aact) As[nxt][lc4+j][lrow] = (&areg.x)[j];
                Ws[nxt][lc4+j][lrow] = (&wreg.x)[j];
            }
        }
        __syncthreads();
    }

    #pragma unroll
    for (int i = 0; i < TM; ++i) {
        int row = bm + ty*TM + i;
        #pragma unroll
        for (int j4 = 0; j4 < 2; ++j4) {
            int col = bn + tx*8 + j4*4;
            if (col < N) {
                float4 o;
                o.x = acc[i][j4*4+0]; o.y = acc[i][j4*4+1];
                o.z = acc[i][j4*4+2]; o.w = acc[i][j4*4+3];
                if (bias) { o.x += bias[col]; o.y += bias[col+1]; o.z += bias[col+2]; o.w += bias[col+3]; }
                *(float4*)&C[(size_t)row*N + col] = o;
            }
        }
    }
}

// ---------------- tf32 helpers ----------------
__device__ __forceinline__ unsigned f2tf32(float f) {
    unsigned u;
    asm("cvt.rna.tf32.f32 %0, %1;" : "=r"(u) : "f"(f));
    return u;
}
__device__ __forceinline__ void mma_tf32(float c[4],
    unsigned a0, unsigned a1, unsigned a2, unsigned a3,
    unsigned b0, unsigned b1)
{
    asm("mma.sync.aligned.m16n8k8.row.col.f32.tf32.tf32.f32 "
        "{%0,%1,%2,%3},{%4,%5,%6,%7},{%8,%9},{%0,%1,%2,%3};"
        : "+f"(c[0]), "+f"(c[1]), "+f"(c[2]), "+f"(c[3])
        : "r"(a0), "r"(a1), "r"(a2), "r"(a3), "r"(b0), "r"(b1));
}

// ---------------- tf32 tensor-core GEMM (V-proj, out-proj) ----------------
__global__ __launch_bounds__(256) void gemm_tc(
    const float* __restrict__ A, const float* __restrict__ W,
    const float* __restrict__ bias, float* __restrict__ C,
    int M, int N, int K)
{
    __shared__ unsigned As[2][8][136];
    __shared__ unsigned Ws[2][8][136];

    const int bm = blockIdx.y * 128, bn = blockIdx.x * 128;
    const int tid = threadIdx.x;
    const int w = tid >> 5, lane = tid & 31;
    const int wm = w >> 2, wn = w & 3;
    const int qr = lane >> 2, qc = lane & 3;
    const int lrow = tid >> 1, lc4 = (tid & 1) * 4;

    const float* Aptr = A + (size_t)(bm + lrow)*K + lc4;
    const float* Wptr = W + (size_t)(bn + lrow)*K + lc4;

    float acc[4][4][4];
    #pragma unroll
    for (int i = 0; i < 4; ++i)
        #pragma unroll
        for (int j = 0; j < 4; ++j)
            #pragma unroll
            for (int r = 0; r < 4; ++r) acc[i][j][r] = 0.f;

    const int nt = K >> 3;
    float4 areg = *(const float4*)Aptr;
    float4 wreg = *(const float4*)Wptr;
    #pragma unroll
    for (int j = 0; j < 4; ++j) {
        As[0][lc4+j][lrow] = f2tf32((&areg.x)[j]);
        Ws[0][lc4+j][lrow] = f2tf32((&wreg.x)[j]);
    }
    __syncthreads();

    for (int t = 0; t < nt; ++t) {
        const int cur = t & 1;
        if (t + 1 < nt) {
            areg = *(const float4*)(Aptr + (t+1)*8);
            wreg = *(const float4*)(Wptr + (t+1)*8);
        }
        unsigned af[4][4], bf[4][2];
        #pragma unroll
        for (int i = 0; i < 4; ++i) {
            int m0 = wm*64 + i*16 + qr;
            af[i][0] = As[cur][qc  ][m0];
            af[i][1] = As[cur][qc  ][m0+8];
            af[i][2] = As[cur][qc+4][m0];
            af[i][3] = As[cur][qc+4][m0+8];
        }
        #pragma unroll
        for (int j = 0; j < 4; ++j) {
            int n0 = wn*32 + j*8 + qr;
            bf[j][0] = Ws[cur][qc  ][n0];
            bf[j][1] = Ws[cur][qc+4][n0];
        }
        #pragma unroll
        for (int i = 0; i < 4; ++i)
            #pragma unroll
            for (int j = 0; j < 4; ++j)
                mma_tf32(acc[i][j], af[i][0], af[i][1], af[i][2], af[i][3],
                         bf[j][0], bf[j][1]);
        if (t + 1 < nt) {
            const int nxt = cur ^ 1;
            #pragma unroll
            for (int j = 0; j < 4; ++j) {
                As[nxt][lc4+j][lrow] = f2tf32((&areg.x)[j]);
                Ws[nxt][lc4+j][lrow] = f2tf32((&wreg.x)[j]);
            }
        }
        __syncthreads();
    }

    #pragma unroll
    for (int i = 0; i < 4; ++i) {
        int r0 = bm + wm*64 + i*16 + qr;
        #pragma unroll
        for (int j = 0; j < 4; ++j) {
            int c0 = bn + wn*32 + j*8 + 2*qc;
            float bx = 0.f, by = 0.f;
            if (bias) { bx = bias[c0]; by = bias[c0+1]; }
            float2 o0, o1;
            o0.x = acc[i][j][0] + bx; o0.y = acc[i][j][1] + by;
            o1.x = acc[i][j][2] + bx; o1.y = acc[i][j][3] + by;
            *(float2*)&C[(size_t)r0*N + c0]     = o0;
            *(float2*)&C[(size_t)(r0+8)*N + c0] = o1;
        }
    }
}

// ---------------- bit packing for boolean heads ----------------
__global__ void pack_bits()
{
    int gw = (blockIdx.x * blockDim.x + threadIdx.x) >> 5;
    int lane = threadIdx.x & 31;
    if (gw >= NTOK) return;
    unsigned q0 = __ballot_sync(0xffffffffu, g_qproj[(size_t)gw*PROJ + lane]       > 0.f);
    unsigned q1 = __ballot_sync(0xffffffffu, g_qproj[(size_t)gw*PROJ + 96 + lane]  > 0.f);
    unsigned k0 = __ballot_sync(0xffffffffu, g_kproj[(size_t)gw*PROJ + lane]       > 0.f);
    unsigned k1 = __ballot_sync(0xffffffffu, g_kproj[(size_t)gw*PROJ + 96 + lane]  > 0.f);
    if (lane == 0) {
        g_qbits[gw*2]   = q0; g_qbits[gw*2+1] = q1;
        g_kbits[gw*2]   = k0; g_kbits[gw*2+1] = k1;
    }
}

// ---------------- fused attention: 64 q x 1 head per block, tf32 mma PV ----
__device__ __forceinline__ float wredmax(float v) {
    #pragma unroll
    for (int o = 16; o; o >>= 1) v = fmaxf(v, __shfl_xor_sync(0xffffffffu, v, o));
    return v;
}
__device__ __forceinline__ float wredsum(float v) {
    #pragma unroll
    for (int o = 16; o; o >>= 1) v += __shfl_xor_sync(0xffffffffu, v, o);
    return v;
}

#define VP_STRIDE 264
#define SC_STRIDE 68
// floats: vp 64*264 | sc 64*68 | qe0,qe1,ke0,ke1 4*2112 | msm,lsm,cf 192 | qb,kb 128
#define ATTN_SMEM_FLOATS (64*VP_STRIDE + 64*SC_STRIDE + 4*2112 + 192 + 128)
#define ATTN_SMEM_BYTES  (ATTN_SMEM_FLOATS*4)

__global__ __launch_bounds__(256) void attn_kernel(const float* __restrict__ t_temp,
                                                   const float* __restrict__ p_fusion)
{
    extern __shared__ __align__(16) float sm[];
    float* vp  = sm;                          // [64][264] tf32 bits
    float* sc  = vp + 64*VP_STRIDE;           // [64][68]
    float* qe0 = sc + 64*SC_STRIDE;           // [64][33]
    float* qe1 = qe0 + 2112;
    float* ke0 = qe1 + 2112;                  // [64][33]
    float* ke1 = ke0 + 2112;
    float* msm = ke1 + 2112;                  // [64]
    float* lsm = msm + 64;
    float* cf  = lsm + 64;
    unsigned* qb = (unsigned*)(cf + 64);      // [64]
    unsigned* kb = qb + 64;                   // [64]

    const int n0   = blockIdx.x * 64;
    const int b    = blockIdx.y;
    const int head = blockIdx.z;
    const int tid  = threadIdx.x;
    const int lane = tid & 31;
    const int w    = tid >> 5;
    const int wm = w >> 1, wn = w & 1;        // warp grid 4x2: 16 rows x 128 cols
    const int qr = lane >> 2, qc = lane & 3;

    float inv_sp = 1.f;
    if (head == 1) inv_sp = 1.f / log1pf(expf(t_temp[0]));
    float fw0 = 0.f, fw1 = 0.f, fw2 = 0.f;
    if (head == 3) {
        float p0 = p_fusion[0], p1 = p_fusion[1], p2 = p_fusion[2];
        float mx = fmaxf(p0, fmaxf(p1, p2));
        float e0 = expf(p0-mx), e1 = expf(p1-mx), e2 = expf(p2-mx);
        float inv = 1.f/(e0+e1+e2);
        fw0 = e0*inv; fw1 = e1*inv; fw2 = e2*inv;
    }

    if (tid < 64) { msm[tid] = -INFINITY; lsm[tid] = 0.f; }

    if (head == 0) {
        if (tid < 64) qb[tid] = g_qbits[(b*SEQ + n0 + tid)*2 + 0];
    } else if (head == 3) {
        if (tid < 64) qb[tid] = g_qbits[(b*SEQ + n0 + tid)*2 + 1];
        for (int j = tid; j < 2048; j += 256) {
            int t = j >> 5, m = j & 31;
            const float* base = &g_qproj[(size_t)(b*SEQ + n0 + t)*PROJ];
            qe0[t*33+m] = base[128+m];
            qe1[t*33+m] = base[160+m];
        }
    } else {
        int off = (head == 1) ? 32 : 64;
        for (int j = tid; j < 2048; j += 256) {
            int t = j >> 5, m = j & 31;
            qe0[t*33+m] = g_qproj[(size_t)(b*SEQ + n0 + t)*PROJ + off + m];
        }
    }

    // mma accumulators: warp owns 16 rows (wm) x 128 cols (wn); 16 n-tiles of 8
    float acc[16][4];
    #pragma unroll
    for (int i = 0; i < 16; ++i)
        #pragma unroll
        for (int j = 0; j < 4; ++j) acc[i][j] = 0.f;

    const float* vp_g = &g_Vp[(size_t)(b*SEQ)*1024 + head*HDIM];
    const int kk  = tid & 63;
    const int qb4 = tid >> 6;

    for (int k0i = 0; k0i < SEQ; k0i += 64) {
        __syncthreads();

        // ---- load Vp tile [64][256] -> tf32, stride 264 ----
        #pragma unroll
        for (int i = 0; i < 16; ++i) {
            int idx = tid + 256*i;
            int row = idx >> 6, c4 = idx & 63;
            float4 v = *(const float4*)&vp_g[(size_t)(k0i+row)*1024 + c4*4];
            unsigned* dst = (unsigned*)&vp[row*VP_STRIDE + c4*4];
            dst[0] = f2tf32(v.x); dst[1] = f2tf32(v.y);
            dst[2] = f2tf32(v.z); dst[3] = f2tf32(v.w);
        }
        if (head == 0) {
            if (tid < 64) kb[tid] = g_kbits[(b*SEQ + k0i + tid)*2 + 0];
        } else if (head == 3) {
            if (tid < 64) kb[tid] = g_kbits[(b*SEQ + k0i + tid)*2 + 1];
            for (int j = tid; j < 2048; j += 256) {
                int t = j >> 5, m = j & 31;
                const float* base = &g_kproj[(size_t)(b*SEQ + k0i + t)*PROJ];
                ke0[t*33+m] = base[128+m];
                ke1[t*33+m] = base[160+m];
            }
        } else {
            int off = (head == 1) ? 32 : 64;
            for (int j = tid; j < 2048; j += 256) {
                int t = j >> 5, m = j & 31;
                ke0[t*33+m] = g_kproj[(size_t)(b*SEQ + k0i + t)*PROJ + off + m];
            }
        }
        __syncthreads();

        // ---- scores ----
        if (head == 0) {
            unsigned kr = kb[kk];
            #pragma unroll
            for (int i = 0; i < 16; ++i) {
                int q = qb4*16 + i;
                int p = __popc(qb[q] ^ kr);
                sc[q*SC_STRIDE + kk] = (1.f - p*(1.f/32.f)) * SCALEF;
            }
        } else if (head == 1) {
            float kr[32];
            #pragma unroll
            for (int m = 0; m < 32; ++m) kr[m] = ke0[kk*33+m];
            #pragma unroll 4
            for (int i = 0; i < 16; ++i) {
                int q = qb4*16 + i;
                const float* qe = &qe0[q*33];
                float mna = INFINITY, mnb = INFINITY;
                #pragma unroll
                for (int m = 0; m < 32; m += 2) {
                    mna = fminf(mna, qe[m]   + kr[m]);
                    mnb = fminf(mnb, qe[m+1] + kr[m+1]);
                }
                sc[q*SC_STRIDE + kk] = -fminf(mna, mnb) * inv_sp;
            }
        } else if (head == 2) {
            float kr[32];
            #pragma unroll
            for (int m = 0; m < 32; ++m) kr[m] = ke0[kk*33+m];
            #pragma unroll 4
            for (int i = 0; i < 16; ++i) {
                int q = qb4*16 + i;
                const float* qe = &qe0[q*33];
                float da = 0.f, db = 0.f;
                #pragma unroll
                for (int m = 0; m < 32; m += 2) {
                    da = fmaf(qe[m],   kr[m],   da);
                    db = fmaf(qe[m+1], kr[m+1], db);
                }
                sc[q*SC_STRIDE + kk] = (da + db) * SCALEF;
            }
        } else {
            float kr0[32], kr1[32];
            #pragma unroll
            for (int m = 0; m < 32; ++m) { kr0[m] = ke0[kk*33+m]; kr1[m] = ke1[kk*33+m]; }
            unsigned kr = kb[kk];
            #pragma unroll 2
            for (int i = 0; i < 16; ++i) {
                int q = qb4*16 + i;
                const float* qe_t = &qe0[q*33];
                const float* qe_r = &qe1[q*33];
                float simb = 1.f - __popc(qb[q] ^ kr)*(1.f/32.f);
                float mna = INFINITY, mnb = INFINITY;
                float da = 0.f, db = 0.f;
                #pragma unroll
                for (int m = 0; m < 32; m += 2) {
                    mna = fminf(mna, qe_t[m]   + kr0[m]);
                    mnb = fminf(mnb, qe_t[m+1] + kr0[m+1]);
                    da = fmaf(qe_r[m],   kr1[m],   da);
                    db = fmaf(qe_r[m+1], kr1[m+1], db);
                }
                sc[q*SC_STRIDE + kk] = (fw0*simb - fw1*fminf(mna,mnb) + fw2*(da+db)) * SCALEF;
            }
        }
        __syncthreads();

        // ---- online softmax: warp w owns rows w*8..w*8+7; write P as tf32 ----
        #pragma unroll
        for (int j = 0; j < 8; ++j) {
            int q = w*8 + j;
            float s0 = sc[q*SC_STRIDE + lane], s1 = sc[q*SC_STRIDE + lane + 32];
            float tm = wredmax(fmaxf(s0, s1));
            float mold = msm[q];
            float mnew = fmaxf(mold, tm);
            float c  = __expf(mold - mnew);
            float p0 = __expf(s0 - mnew), p1 = __expf(s1 - mnew);
            sc[q*SC_STRIDE + lane]      = __uint_as_float(f2tf32(p0));
            sc[q*SC_STRIDE + lane + 32] = __uint_as_float(f2tf32(p1));
            float ls = wredsum(p0 + p1);
            if (lane == 0) { msm[q] = mnew; lsm[q] = lsm[q]*c + ls; cf[q] = c; }
        }
        __syncthreads();

        // ---- PV via tf32 mma: rescale fragments, then 8 k-steps x 16 n-tiles ----
        {
            float clo = cf[wm*16 + qr], chi = cf[wm*16 + qr + 8];
            #pragma unroll
            for (int nt = 0; nt < 16; ++nt) {
                acc[nt][0] *= clo; acc[nt][1] *= clo;
                acc[nt][2] *= chi; acc[nt][3] *= chi;
            }
            const unsigned* scu = (const unsigned*)sc;
            const unsigned* vpu = (const unsigned*)vp;
            const int rlo = (wm*16 + qr)*SC_STRIDE, rhi = rlo + 8*SC_STRIDE;
            #pragma unroll
            for (int ks = 0; ks < 8; ++ks) {
                const int k0 = ks*8;
                unsigned a0 = scu[rlo + k0 + qc];
                unsigned a1 = scu[rhi + k0 + qc];
                unsigned a2 = scu[rlo + k0 + qc + 4];
                unsigned a3 = scu[rhi + k0 + qc + 4];
                const unsigned* v0 = &vpu[(k0+qc)*VP_STRIDE   + wn*128 + qr];
                const unsigned* v1 = &vpu[(k0+qc+4)*VP_STRIDE + wn*128 + qr];
                #pragma unroll
                for (int nt = 0; nt < 16; ++nt)
                    mma_tf32(acc[nt], a0, a1, a2, a3, v0[nt*8], v1[nt*8]);
            }
        }
    }

    // ---- epilogue: normalize + write fragments ----
    {
        int rlo = wm*16 + qr, rhi = rlo + 8;
        float il_lo = 1.f / lsm[rlo], il_hi = 1.f / lsm[rhi];
        float* out_lo = &g_cat[(size_t)(b*SEQ + n0 + rlo)*1024 + head*HDIM + wn*128];
        float* out_hi = &g_cat[(size_t)(b*SEQ + n0 + rhi)*1024 + head*HDIM + wn*128];
        #pragma unroll
        for (int nt = 0; nt < 16; ++nt) {
            int c0 = nt*8 + 2*qc;
            float2 o0, o1;
            o0.x = acc[nt][0]*il_lo; o0.y = acc[nt][1]*il_lo;
            o1.x = acc[nt][2]*il_hi; o1.y = acc[nt][3]*il_hi;
            *(float2*)&out_lo[c0] = o0;
            *(float2*)&out_hi[c0] = o1;
        }
    }
}

// ---------------- host launch ----------------
extern "C" void kernel_launch(void* const* d_in, const int* in_sizes, int n_in,
                              void* d_out, int out_size)
{
    const float* Q        = (const float*)d_in[0];
    const float* K        = (const float*)d_in[1];
    const float* V        = (const float*)d_in[2];
    const float* bq_w     = (const float*)d_in[3];
    const float* bq_b     = (const float*)d_in[4];
    const float* bk_w     = (const float*)d_in[5];
    const float* bk_b     = (const float*)d_in[6];
    const float* b_v      = (const float*)d_in[7];
    const float* tq_w     = (const float*)d_in[8];
    const float* tq_b     = (const float*)d_in[9];
    const float* tk_w     = (const float*)d_in[10];
    const float* tk_b     = (const float*)d_in[11];
    const float* t_v      = (const float*)d_in[12];
    const float* t_temp   = (const float*)d_in[13];
    const float* rq_w     = (const float*)d_in[14];
    const float* rq_b     = (const float*)d_in[15];
    const float* rk_w     = (const float*)d_in[16];
    const float* rk_b     = (const float*)d_in[17];
    const float* r_v      = (const float*)d_in[18];
    const float* pq_w     = (const float*)d_in[19];
    const float* pq_b     = (const float*)d_in[20];
    const float* pk_w     = (const float*)d_in[21];
    const float* pk_b     = (const float*)d_in[22];
    const float* p_v      = (const float*)d_in[23];
    const float* p_fusion = (const float*)d_in[24];
    const float* out_w    = (const float*)d_in[25];
    const float* out_b    = (const float*)d_in[26];
    float* out = (float*)d_out;

    void *pWq, *pWk, *pBq, *pBk, *pWv, *pqp, *pkp, *pVp, *pcat;
    cudaGetSymbolAddress(&pWq,  g_Wq);
    cudaGetSymbolAddress(&pWk,  g_Wk);
    cudaGetSymbolAddress(&pBq,  g_Bq);
    cudaGetSymbolAddress(&pBk,  g_Bk);
    cudaGetSymbolAddress(&pWv,  g_Wv);
    cudaGetSymbolAddress(&pqp,  g_qproj);
    cudaGetSymbolAddress(&pkp,  g_kproj);
    cudaGetSymbolAddress(&pVp,  g_Vp);
    cudaGetSymbolAddress(&pcat, g_cat);

    pack_weights<<<256, 256>>>(bq_w, tq_w, rq_w, pq_w, bq_b, tq_b, rq_b, pq_b,
                               bk_w, tk_w, rk_w, pk_w, bk_b, tk_b, rk_b, pk_b,
                               b_v, t_v, r_v, p_v);

    // Q/K projections (exact fp32): [2048 x 192 x 1024], z selects Q/K
    gemm_db<64,4><<<dim3(2, 32, 2), 256>>>(
        Q, K, (const float*)pWq, (const float*)pWk,
        (const float*)pBq, (const float*)pBk,
        (float*)pqp, (float*)pkp, NTOK, PROJ, DIM);

    // V projection (tf32 tensor cores): [2048 x 1024 x 1024]
    gemm_tc<<<dim3(8, 16), 256>>>(V, (const float*)pWv, nullptr,
                                  (float*)pVp, NTOK, 4*HDIM, DIM);

    pack_bits<<<NTOK*32/256, 256>>>();

    cudaFuncSetAttribute(attn_kernel, cudaFuncAttributeMaxDynamicSharedMemorySize,
                         ATTN_SMEM_BYTES);
    attn_kernel<<<dim3(SEQ/64, BATCH, 4), 256, ATTN_SMEM_BYTES>>>(t_temp, p_fusion);

    // output projection (tf32 tensor cores): [2048 x 1024 x 1024]
    gemm_tc<<<dim3(8, 16), 256>>>((const float*)pcat, out_w, out_b,
                                  out, NTOK, DIM, DIM);
}